// round 10
// baseline (speedup 1.0000x reference)
#include <cuda_runtime.h>

// ---------------------------------------------------------------------------
// PPN on 3-level sparse voxel grid — FFMA2 convs, occupancy-optimized:
// RN=2 microtile + 256-thread blocks + launch_bounds minBlocks to double
// resident warps (R9 evidence: binder is occupancy/issue, not fma pipe).
// output: points [N3,10] | ppn1 [N1,6] | ppn2 [N2,6] | mask1 [N1] | mask2 [N2]
// ---------------------------------------------------------------------------

#define N1_MAX 65536
#define N2_MAX 262144
#define N3_MAX 262144

__device__ float g_y1[(size_t)N1_MAX * 80];
__device__ float g_f2m[(size_t)N2_MAX * 48];
__device__ float g_y2[(size_t)N2_MAX * 48];
__device__ float g_f3m[(size_t)N3_MAX * 16];
__device__ float g_z[(size_t)N3_MAX * 16];

typedef unsigned long long ull;

__device__ __forceinline__ ull pk2(float x, float y) {
    ull r; asm("mov.b64 %0, {%1, %2};" : "=l"(r) : "f"(x), "f"(y)); return r;
}
__device__ __forceinline__ void fma2(ull& d, ull a, ull b) {
    asm("fma.rn.f32x2 %0, %1, %2, %0;" : "+l"(d) : "l"(a), "l"(b));
}
__device__ __forceinline__ float2 up2(ull v) {
    float a, b; asm("mov.b64 {%0, %1}, %2;" : "=f"(a), "=f"(b) : "l"(v));
    return make_float2(a, b);
}

// ---------------------------------------------------------------------------
// Submanifold conv via f32x2, cooperative smem staging per (k, CIN-chunk).
// out[n,d] = sum_k sum_c feat[nbr[n,k],c] * W[k,c,d]
// ---------------------------------------------------------------------------
template <int CIN, int COUT, int TN, int RN, int RD, int NTX, int CCH, int MINB>
__global__ __launch_bounds__(NTX*(TN/RN), MINB)
void subconv2(const float* __restrict__ feat, const int* __restrict__ nbr,
              const float* __restrict__ W, float* __restrict__ out, int N) {
    constexpr int CP = CCH + 4;
    constexpr int NTY = TN / RN;
    constexpr int NTH = NTX * NTY;
    static_assert(NTH == 128 || NTH == 256, "thread count");
    static_assert(CIN % CCH == 0 && CCH % 4 == 0 && RD % 4 == 0, "");
    constexpr int NH = CIN / CCH;
    constexpr int VEC = CCH / 4;
    constexpr int NP = RD / 2;
    constexpr int NU = RD / 4;

    extern __shared__ float sh[];
    float* sW = sh;                        // [CCH][COUT] natural layout
    float* sF = sh + CCH * COUT;           // [TN][CP] padded rows
    __shared__ int sIdx[TN];

    const int tid = threadIdx.x;
    const int tx = tid % NTX, ty = tid / NTX;
    const int n0 = blockIdx.x * TN;
    const int nb = ty * RN, db = tx * RD;

    ull acc[RN][NP];
#pragma unroll
    for (int i = 0; i < RN; ++i)
#pragma unroll
        for (int p = 0; p < NP; ++p) acc[i][p] = 0ULL;

    for (int k = 0; k < 27; ++k) {
        for (int i = tid; i < TN; i += NTH) {
            int n = n0 + i;
            sIdx[i] = (n < N) ? nbr[n * 27 + k] : N;
        }
        const float* Wk = W + (size_t)k * CIN * COUT;
#pragma unroll
        for (int h = 0; h < NH; ++h) {
            __syncthreads();   // protect sW/sF reuse; orders sIdx for h==0
            for (int i = tid; i < CCH * COUT; i += NTH)
                sW[i] = Wk[h * CCH * COUT + i];
            const int bc = h * CCH;
            for (int i = tid; i < TN * VEC; i += NTH) {
                int n = i / VEC, c4 = (i - n * VEC) * 4;
                int idx = sIdx[n];
                float4 v = make_float4(0.f, 0.f, 0.f, 0.f);
                if ((unsigned)idx < (unsigned)N)
                    v = *reinterpret_cast<const float4*>(
                        feat + (size_t)idx * CIN + bc + c4);
                *reinterpret_cast<float4*>(sF + n * CP + c4) = v;
            }
            __syncthreads();

#pragma unroll
            for (int c4 = 0; c4 < CCH; c4 += 4) {
                float4 A[RN];
#pragma unroll
                for (int i = 0; i < RN; ++i)
                    A[i] = *reinterpret_cast<const float4*>(
                        sF + (nb + i) * CP + c4);
#pragma unroll
                for (int cc = 0; cc < 4; ++cc) {
                    ull as[RN];
#pragma unroll
                    for (int i = 0; i < RN; ++i) {
                        float v = (cc == 0) ? A[i].x : (cc == 1) ? A[i].y
                                 : (cc == 2) ? A[i].z : A[i].w;
                        as[i] = pk2(v, v);
                    }
                    const float* wrow = sW + (c4 + cc) * COUT + db;
#pragma unroll
                    for (int u = 0; u < NU; ++u) {
                        float4 B = *reinterpret_cast<const float4*>(wrow + 4 * u);
                        ull b0 = pk2(B.x, B.y), b1 = pk2(B.z, B.w);
#pragma unroll
                        for (int i = 0; i < RN; ++i) {
                            fma2(acc[i][2 * u], as[i], b0);
                            fma2(acc[i][2 * u + 1], as[i], b1);
                        }
                    }
                }
            }
        }
    }

#pragma unroll
    for (int i = 0; i < RN; ++i) {
        int n = n0 + nb + i;
        if (n < N) {
#pragma unroll
            for (int u = 0; u < NU; ++u) {
                float2 p0 = up2(acc[i][2 * u]), p1 = up2(acc[i][2 * u + 1]);
                float4 o = make_float4(p0.x, p0.y, p1.x, p1.y);
                *reinterpret_cast<float4*>(out + (size_t)n * COUT + db + 4 * u) = o;
            }
        }
    }
}

// ---------------------------------------------------------------------------
// Score head (Cout=2) + ppn concat + softmax-threshold mask (proven form).
// softmax([s0,s1])[1] > 0.8  <=>  1/(1+exp(s0-s1)) > 0.8
// ---------------------------------------------------------------------------
template <int CIN>
__global__ void score_ppn_mask(const float* __restrict__ feat,
                               const int* __restrict__ nbr,
                               const float* __restrict__ Ws,
                               const int* __restrict__ coords,
                               float* __restrict__ ppn,
                               float* __restrict__ mask, int N) {
    __shared__ float sW[27 * 2 * CIN];  // [k][d][c]
    for (int i = threadIdx.x; i < 27 * CIN * 2; i += blockDim.x) {
        int k = i / (CIN * 2);
        int r = i - k * (CIN * 2);
        int c = r >> 1, d = r & 1;
        sW[(k * 2 + d) * CIN + c] = Ws[i];
    }
    __syncthreads();
    int n = blockIdx.x * blockDim.x + threadIdx.x;
    if (n >= N) return;

    float a0 = 0.f, a1 = 0.f;
    for (int k = 0; k < 27; ++k) {
        int idx = nbr[n * 27 + k];
        if ((unsigned)idx < (unsigned)N) {
            const float4* fr = reinterpret_cast<const float4*>(feat + (size_t)idx * CIN);
            const float4* w0 = reinterpret_cast<const float4*>(sW + (k * 2 + 0) * CIN);
            const float4* w1 = reinterpret_cast<const float4*>(sW + (k * 2 + 1) * CIN);
#pragma unroll
            for (int j = 0; j < CIN / 4; ++j) {
                float4 v = fr[j], x = w0[j], y = w1[j];
                a0 += v.x * x.x + v.y * x.y + v.z * x.z + v.w * x.w;
                a1 += v.x * y.x + v.y * y.y + v.z * y.z + v.w * y.w;
            }
        }
    }
    ppn[(size_t)n * 6 + 0] = (float)coords[n * 4 + 0];
    ppn[(size_t)n * 6 + 1] = (float)coords[n * 4 + 1];
    ppn[(size_t)n * 6 + 2] = (float)coords[n * 4 + 2];
    ppn[(size_t)n * 6 + 3] = (float)coords[n * 4 + 3];
    ppn[(size_t)n * 6 + 4] = a0;
    ppn[(size_t)n * 6 + 5] = a1;
    float p = 1.f / (1.f + expf(a0 - a1));
    mask[n] = (p > 0.8f) ? 1.f : 0.f;
}

// featm[j,:] = feat[j,:] * mask[parent[j]]
template <int C>
__global__ void apply_att(const float* __restrict__ feat,
                          const int* __restrict__ parent,
                          const float* __restrict__ mask,
                          float* __restrict__ outF, int N) {
    int i = blockIdx.x * blockDim.x + threadIdx.x;
    int total = N * (C / 4);
    if (i >= total) return;
    int n = i / (C / 4);
    float m = mask[parent[n]];
    float4 v = reinterpret_cast<const float4*>(feat)[i];
    v.x *= m; v.y *= m; v.z *= m; v.w *= m;
    reinterpret_cast<float4*>(outF)[i] = v;
}

// Fine heads fused (proven form): points[n, 0:3|3:5|5:10].
__global__ void heads_kernel(const float* __restrict__ z,
                             const int* __restrict__ nbr,
                             const float* __restrict__ Wp,
                             const float* __restrict__ Wsc,
                             const float* __restrict__ Wt,
                             float* __restrict__ points, int N) {
    __shared__ float sW[27 * 10 * 16];  // [k][d][c]
    for (int i = threadIdx.x; i < 27 * 16 * 3; i += blockDim.x) {
        int k = i / 48; int r = i - k * 48; int c = r / 3; int d = r - c * 3;
        sW[(k * 10 + d) * 16 + c] = Wp[i];
    }
    for (int i = threadIdx.x; i < 27 * 16 * 2; i += blockDim.x) {
        int k = i / 32; int r = i - k * 32; int c = r >> 1; int d = r & 1;
        sW[(k * 10 + 3 + d) * 16 + c] = Wsc[i];
    }
    for (int i = threadIdx.x; i < 27 * 16 * 5; i += blockDim.x) {
        int k = i / 80; int r = i - k * 80; int c = r / 5; int d = r - c * 5;
        sW[(k * 10 + 5 + d) * 16 + c] = Wt[i];
    }
    __syncthreads();
    int n = blockIdx.x * blockDim.x + threadIdx.x;
    if (n >= N) return;

    float acc[10];
#pragma unroll
    for (int d = 0; d < 10; ++d) acc[d] = 0.f;

    for (int k = 0; k < 27; ++k) {
        int idx = nbr[n * 27 + k];
        if ((unsigned)idx < (unsigned)N) {
            const float4* zr = reinterpret_cast<const float4*>(z + (size_t)idx * 16);
            float4 v0 = zr[0], v1 = zr[1], v2 = zr[2], v3 = zr[3];
#pragma unroll
            for (int d = 0; d < 10; ++d) {
                const float4* wr = reinterpret_cast<const float4*>(sW + (k * 10 + d) * 16);
                float4 w0 = wr[0], w1 = wr[1], w2 = wr[2], w3 = wr[3];
                acc[d] += v0.x * w0.x + v0.y * w0.y + v0.z * w0.z + v0.w * w0.w
                        + v1.x * w1.x + v1.y * w1.y + v1.z * w1.z + v1.w * w1.w
                        + v2.x * w2.x + v2.y * w2.y + v2.z * w2.z + v2.w * w2.w
                        + v3.x * w3.x + v3.y * w3.y + v3.z * w3.z + v3.w * w3.w;
            }
        }
    }
#pragma unroll
    for (int d = 0; d < 10; ++d) points[(size_t)n * 10 + d] = acc[d];
}

// ---------------------------------------------------------------------------
static constexpr int smem_sub(int CCH, int COUT, int TN) {
    return (CCH * COUT + TN * (CCH + 4) + 32) * (int)sizeof(float);
}

extern "C" void kernel_launch(void* const* d_in, const int* in_sizes, int n_in,
                              void* d_out, int out_size) {
    const float* feat1 = (const float*)d_in[0];
    const float* feat2 = (const float*)d_in[1];
    const float* feat3 = (const float*)d_in[2];
    const float* W1  = (const float*)d_in[3];
    const float* W1s = (const float*)d_in[4];
    const float* W2  = (const float*)d_in[5];
    const float* W2s = (const float*)d_in[6];
    const float* W3  = (const float*)d_in[7];
    const float* W3p = (const float*)d_in[8];
    const float* W3s = (const float*)d_in[9];
    const float* W3t = (const float*)d_in[10];
    const int* nbr1 = (const int*)d_in[11];
    const int* nbr2 = (const int*)d_in[12];
    const int* nbr3 = (const int*)d_in[13];
    const int* parent2 = (const int*)d_in[14];
    const int* parent3 = (const int*)d_in[15];
    const int* coords1 = (const int*)d_in[16];
    const int* coords2 = (const int*)d_in[17];

    const int N1 = in_sizes[0] / 80;
    const int N2 = in_sizes[1] / 48;
    const int N3 = in_sizes[2] / 16;

    float* out = (float*)d_out;
    float* points = out;
    float* ppn1  = points + (size_t)N3 * 10;
    float* ppn2  = ppn1 + (size_t)N1 * 6;
    float* mask1 = ppn2 + (size_t)N2 * 6;
    float* mask2 = mask1 + N1;

    float *y1, *f2m, *y2, *f3m, *z;
    cudaGetSymbolAddress((void**)&y1, g_y1);
    cudaGetSymbolAddress((void**)&f2m, g_f2m);
    cudaGetSymbolAddress((void**)&y2, g_y2);
    cudaGetSymbolAddress((void**)&f3m, g_f3m);
    cudaGetSymbolAddress((void**)&z, g_z);

    // --- Level 1 (coarse, 80ch): unchunked, RN=2, 256thr, 68.6KB smem ---
    cudaFuncSetAttribute((const void*)subconv2<80, 80, 128, 2, 20, 4, 80, 3>,
                         cudaFuncAttributeMaxDynamicSharedMemorySize,
                         smem_sub(80, 80, 128));
    subconv2<80, 80, 128, 2, 20, 4, 80, 3>
        <<<(N1 + 127) / 128, 256, smem_sub(80, 80, 128)>>>(feat1, nbr1, W1, y1, N1);
    score_ppn_mask<80><<<(N1 + 255) / 256, 256>>>(y1, nbr1, W1s, coords1, ppn1, mask1, N1);

    // --- Level 2 (mid, 48ch): RN=2, 256thr, minBlocks=4 -> 50% occ target ---
    apply_att<48><<<(N2 * 12 + 255) / 256, 256>>>(feat2, parent2, mask1, f2m, N2);
    subconv2<48, 48, 128, 2, 12, 4, 48, 4>
        <<<(N2 + 127) / 128, 256, smem_sub(48, 48, 128)>>>(f2m, nbr2, W2, y2, N2);
    score_ppn_mask<48><<<(N2 + 255) / 256, 256>>>(y2, nbr2, W2s, coords2, ppn2, mask2, N2);

    // --- Level 3 (fine, 16ch): R9-proven config ---
    apply_att<16><<<(N3 * 4 + 255) / 256, 256>>>(feat3, parent3, mask2, f3m, N3);
    subconv2<16, 16, 256, 8, 4, 4, 16, 6>
        <<<(N3 + 255) / 256, 128, smem_sub(16, 16, 256)>>>(f3m, nbr3, W3, z, N3);
    heads_kernel<<<(N3 + 255) / 256, 256>>>(z, nbr3, W3p, W3s, W3t, points, N3);
}

// round 11
// speedup vs baseline: 1.2928x; 1.2928x over previous
#include <cuda_runtime.h>

// ---------------------------------------------------------------------------
// PPN on 3-level sparse voxel grid — FFMA2 convs (R4-proven shapes) with
// mask-fused gather + per-stage all-zero SKIP (always-correct, adaptive:
// evidence says ref masks are all/mostly zero, so masked convs collapse).
// output: points [N3,10] | ppn1 [N1,6] | ppn2 [N2,6] | mask1 [N1] | mask2 [N2]
// ---------------------------------------------------------------------------

#define N1_MAX 65536
#define N2_MAX 262144
#define N3_MAX 262144

__device__ float g_y1[(size_t)N1_MAX * 80];
__device__ float g_y2[(size_t)N2_MAX * 48];
__device__ float g_z[(size_t)N3_MAX * 16];

typedef unsigned long long ull;

__device__ __forceinline__ ull pk2(float x, float y) {
    ull r; asm("mov.b64 %0, {%1, %2};" : "=l"(r) : "f"(x), "f"(y)); return r;
}
__device__ __forceinline__ void fma2(ull& d, ull a, ull b) {
    asm("fma.rn.f32x2 %0, %1, %2, %0;" : "+l"(d) : "l"(a), "l"(b));
}
__device__ __forceinline__ float2 up2(ull v) {
    float a, b; asm("mov.b64 {%0, %1}, %2;" : "=f"(a), "=f"(b) : "l"(v));
    return make_float2(a, b);
}

// ---------------------------------------------------------------------------
// Unmasked conv (level 1) — R4/R9-proven cooperative-staging core.
// ---------------------------------------------------------------------------
template <int CIN, int COUT, int TN, int RN, int RD, int NTX, int CCH>
__global__ __launch_bounds__(128)
void subconv2(const float* __restrict__ feat, const int* __restrict__ nbr,
              const float* __restrict__ W, float* __restrict__ out, int N) {
    constexpr int CP = CCH + 4;
    constexpr int NTY = TN / RN;
    constexpr int NTH = NTX * NTY;
    static_assert(NTH == 128, "128 threads");
    static_assert(CIN % CCH == 0 && CCH % 4 == 0 && RD % 4 == 0, "");
    constexpr int NH = CIN / CCH;
    constexpr int VEC = CCH / 4;
    constexpr int NP = RD / 2;
    constexpr int NU = RD / 4;

    extern __shared__ float sh[];
    float* sW = sh;
    float* sF = sh + CCH * COUT;
    __shared__ int sIdx[TN];

    const int tid = threadIdx.x;
    const int tx = tid % NTX, ty = tid / NTX;
    const int n0 = blockIdx.x * TN;
    const int nb = ty * RN, db = tx * RD;

    ull acc[RN][NP];
#pragma unroll
    for (int i = 0; i < RN; ++i)
#pragma unroll
        for (int p = 0; p < NP; ++p) acc[i][p] = 0ULL;

    for (int k = 0; k < 27; ++k) {
        for (int i = tid; i < TN; i += NTH) {
            int n = n0 + i;
            sIdx[i] = (n < N) ? nbr[n * 27 + k] : N;
        }
        const float* Wk = W + (size_t)k * CIN * COUT;
#pragma unroll
        for (int h = 0; h < NH; ++h) {
            __syncthreads();
            for (int i = tid; i < CCH * COUT; i += NTH)
                sW[i] = Wk[h * CCH * COUT + i];
            const int bc = h * CCH;
            for (int i = tid; i < TN * VEC; i += NTH) {
                int n = i / VEC, c4 = (i - n * VEC) * 4;
                int idx = sIdx[n];
                float4 v = make_float4(0.f, 0.f, 0.f, 0.f);
                if ((unsigned)idx < (unsigned)N)
                    v = *reinterpret_cast<const float4*>(
                        feat + (size_t)idx * CIN + bc + c4);
                *reinterpret_cast<float4*>(sF + n * CP + c4) = v;
            }
            __syncthreads();

#pragma unroll
            for (int c4 = 0; c4 < CCH; c4 += 4) {
                float4 A[RN];
#pragma unroll
                for (int i = 0; i < RN; ++i)
                    A[i] = *reinterpret_cast<const float4*>(
                        sF + (nb + i) * CP + c4);
#pragma unroll
                for (int cc = 0; cc < 4; ++cc) {
                    ull as[RN];
#pragma unroll
                    for (int i = 0; i < RN; ++i) {
                        float v = (cc == 0) ? A[i].x : (cc == 1) ? A[i].y
                                 : (cc == 2) ? A[i].z : A[i].w;
                        as[i] = pk2(v, v);
                    }
                    const float* wrow = sW + (c4 + cc) * COUT + db;
#pragma unroll
                    for (int u = 0; u < NU; ++u) {
                        float4 B = *reinterpret_cast<const float4*>(wrow + 4 * u);
                        ull b0 = pk2(B.x, B.y), b1 = pk2(B.z, B.w);
#pragma unroll
                        for (int i = 0; i < RN; ++i) {
                            fma2(acc[i][2 * u], as[i], b0);
                            fma2(acc[i][2 * u + 1], as[i], b1);
                        }
                    }
                }
            }
        }
    }

#pragma unroll
    for (int i = 0; i < RN; ++i) {
        int n = n0 + nb + i;
        if (n < N) {
#pragma unroll
            for (int u = 0; u < NU; ++u) {
                float2 p0 = up2(acc[i][2 * u]), p1 = up2(acc[i][2 * u + 1]);
                float4 o = make_float4(p0.x, p0.y, p1.x, p1.y);
                *reinterpret_cast<float4*>(out + (size_t)n * COUT + db + 4 * u) = o;
            }
        }
    }
}

// ---------------------------------------------------------------------------
// Masked conv (levels 2/3): out[n,d] = sum_k sum_c mask[parent[j]]*feat[j,c]
// *W[k,c,d], j=nbr[n,k]. Per-k all-zero-mask stages are SKIPPED exactly.
// ---------------------------------------------------------------------------
template <int CIN, int COUT, int TN, int RN, int RD, int NTX>
__global__ __launch_bounds__(128)
void subconv2m(const float* __restrict__ feat, const int* __restrict__ nbr,
               const float* __restrict__ W,
               const int* __restrict__ parent, const float* __restrict__ mask,
               float* __restrict__ out, int N) {
    constexpr int CP = CIN + 4;
    constexpr int NTY = TN / RN;
    constexpr int NTH = NTX * NTY;
    static_assert(NTH == 128, "128 threads");
    static_assert(CIN % 4 == 0 && RD % 4 == 0, "");
    constexpr int VEC = CIN / 4;
    constexpr int NP = RD / 2;
    constexpr int NU = RD / 4;

    extern __shared__ float sh[];
    float* sW = sh;                        // [CIN][COUT]
    float* sF = sh + CIN * COUT;           // [TN][CP]
    __shared__ int sIdx[TN];
    __shared__ float sM[TN];

    const int tid = threadIdx.x;
    const int tx = tid % NTX, ty = tid / NTX;
    const int n0 = blockIdx.x * TN;
    const int nb = ty * RN, db = tx * RD;

    ull acc[RN][NP];
#pragma unroll
    for (int i = 0; i < RN; ++i)
#pragma unroll
        for (int p = 0; p < NP; ++p) acc[i][p] = 0ULL;

    for (int k = 0; k < 27; ++k) {
        // (A) stage indices + masks (disjoint from sW/sF still being read)
        int myAny = 0;
        for (int i = tid; i < TN; i += NTH) {
            int n = n0 + i;
            int idx = (n < N) ? nbr[n * 27 + k] : N;
            float m = ((unsigned)idx < (unsigned)N) ? mask[parent[idx]] : 0.f;
            sIdx[i] = idx;
            sM[i] = m;
            myAny |= (m != 0.f);
        }
        // barrier + block-OR; also orders prev compute before sF/sW rewrite
        if (!__syncthreads_or(myAny)) continue;   // exact: zero contribution

        const float* Wk = W + (size_t)k * CIN * COUT;
        for (int i = tid; i < CIN * COUT; i += NTH) sW[i] = Wk[i];
        for (int i = tid; i < TN * VEC; i += NTH) {
            int n = i / VEC, c4 = (i - n * VEC) * 4;
            int idx = sIdx[n];
            float4 v = make_float4(0.f, 0.f, 0.f, 0.f);
            if ((unsigned)idx < (unsigned)N) {
                float m = sM[n];
                if (m != 0.f) {
                    v = *reinterpret_cast<const float4*>(
                        feat + (size_t)idx * CIN + c4);
                    v.x *= m; v.y *= m; v.z *= m; v.w *= m;
                }
            }
            *reinterpret_cast<float4*>(sF + n * CP + c4) = v;
        }
        __syncthreads();

#pragma unroll
        for (int c4 = 0; c4 < CIN; c4 += 4) {
            float4 A[RN];
#pragma unroll
            for (int i = 0; i < RN; ++i)
                A[i] = *reinterpret_cast<const float4*>(sF + (nb + i) * CP + c4);
#pragma unroll
            for (int cc = 0; cc < 4; ++cc) {
                ull as[RN];
#pragma unroll
                for (int i = 0; i < RN; ++i) {
                    float v = (cc == 0) ? A[i].x : (cc == 1) ? A[i].y
                             : (cc == 2) ? A[i].z : A[i].w;
                    as[i] = pk2(v, v);
                }
                const float* wrow = sW + (c4 + cc) * COUT + db;
#pragma unroll
                for (int u = 0; u < NU; ++u) {
                    float4 B = *reinterpret_cast<const float4*>(wrow + 4 * u);
                    ull b0 = pk2(B.x, B.y), b1 = pk2(B.z, B.w);
#pragma unroll
                    for (int i = 0; i < RN; ++i) {
                        fma2(acc[i][2 * u], as[i], b0);
                        fma2(acc[i][2 * u + 1], as[i], b1);
                    }
                }
            }
        }
    }

#pragma unroll
    for (int i = 0; i < RN; ++i) {
        int n = n0 + nb + i;
        if (n < N) {
#pragma unroll
            for (int u = 0; u < NU; ++u) {
                float2 p0 = up2(acc[i][2 * u]), p1 = up2(acc[i][2 * u + 1]);
                float4 o = make_float4(p0.x, p0.y, p1.x, p1.y);
                *reinterpret_cast<float4*>(out + (size_t)n * COUT + db + 4 * u) = o;
            }
        }
    }
}

// ---------------------------------------------------------------------------
// Score head (Cout=2) + ppn concat + softmax-threshold mask (proven form).
// softmax([s0,s1])[1] > 0.8  <=>  1/(1+exp(s0-s1)) > 0.8
// ---------------------------------------------------------------------------
template <int CIN>
__global__ void score_ppn_mask(const float* __restrict__ feat,
                               const int* __restrict__ nbr,
                               const float* __restrict__ Ws,
                               const int* __restrict__ coords,
                               float* __restrict__ ppn,
                               float* __restrict__ mask, int N) {
    __shared__ float sW[27 * 2 * CIN];  // [k][d][c]
    for (int i = threadIdx.x; i < 27 * CIN * 2; i += blockDim.x) {
        int k = i / (CIN * 2);
        int r = i - k * (CIN * 2);
        int c = r >> 1, d = r & 1;
        sW[(k * 2 + d) * CIN + c] = Ws[i];
    }
    __syncthreads();
    int n = blockIdx.x * blockDim.x + threadIdx.x;
    if (n >= N) return;

    float a0 = 0.f, a1 = 0.f;
    for (int k = 0; k < 27; ++k) {
        int idx = nbr[n * 27 + k];
        if ((unsigned)idx < (unsigned)N) {
            const float4* fr = reinterpret_cast<const float4*>(feat + (size_t)idx * CIN);
            const float4* w0 = reinterpret_cast<const float4*>(sW + (k * 2 + 0) * CIN);
            const float4* w1 = reinterpret_cast<const float4*>(sW + (k * 2 + 1) * CIN);
#pragma unroll
            for (int j = 0; j < CIN / 4; ++j) {
                float4 v = fr[j], x = w0[j], y = w1[j];
                a0 += v.x * x.x + v.y * x.y + v.z * x.z + v.w * x.w;
                a1 += v.x * y.x + v.y * y.y + v.z * y.z + v.w * y.w;
            }
        }
    }
    ppn[(size_t)n * 6 + 0] = (float)coords[n * 4 + 0];
    ppn[(size_t)n * 6 + 1] = (float)coords[n * 4 + 1];
    ppn[(size_t)n * 6 + 2] = (float)coords[n * 4 + 2];
    ppn[(size_t)n * 6 + 3] = (float)coords[n * 4 + 3];
    ppn[(size_t)n * 6 + 4] = a0;
    ppn[(size_t)n * 6 + 5] = a1;
    float p = 1.f / (1.f + expf(a0 - a1));
    mask[n] = (p > 0.8f) ? 1.f : 0.f;
}

// Fine heads fused (proven form): points[n, 0:3|3:5|5:10].
__global__ void heads_kernel(const float* __restrict__ z,
                             const int* __restrict__ nbr,
                             const float* __restrict__ Wp,
                             const float* __restrict__ Wsc,
                             const float* __restrict__ Wt,
                             float* __restrict__ points, int N) {
    __shared__ float sW[27 * 10 * 16];  // [k][d][c]
    for (int i = threadIdx.x; i < 27 * 16 * 3; i += blockDim.x) {
        int k = i / 48; int r = i - k * 48; int c = r / 3; int d = r - c * 3;
        sW[(k * 10 + d) * 16 + c] = Wp[i];
    }
    for (int i = threadIdx.x; i < 27 * 16 * 2; i += blockDim.x) {
        int k = i / 32; int r = i - k * 32; int c = r >> 1; int d = r & 1;
        sW[(k * 10 + 3 + d) * 16 + c] = Wsc[i];
    }
    for (int i = threadIdx.x; i < 27 * 16 * 5; i += blockDim.x) {
        int k = i / 80; int r = i - k * 80; int c = r / 5; int d = r - c * 5;
        sW[(k * 10 + 5 + d) * 16 + c] = Wt[i];
    }
    __syncthreads();
    int n = blockIdx.x * blockDim.x + threadIdx.x;
    if (n >= N) return;

    float acc[10];
#pragma unroll
    for (int d = 0; d < 10; ++d) acc[d] = 0.f;

    for (int k = 0; k < 27; ++k) {
        int idx = nbr[n * 27 + k];
        if ((unsigned)idx < (unsigned)N) {
            const float4* zr = reinterpret_cast<const float4*>(z + (size_t)idx * 16);
            float4 v0 = zr[0], v1 = zr[1], v2 = zr[2], v3 = zr[3];
#pragma unroll
            for (int d = 0; d < 10; ++d) {
                const float4* wr = reinterpret_cast<const float4*>(sW + (k * 10 + d) * 16);
                float4 w0 = wr[0], w1 = wr[1], w2 = wr[2], w3 = wr[3];
                acc[d] += v0.x * w0.x + v0.y * w0.y + v0.z * w0.z + v0.w * w0.w
                        + v1.x * w1.x + v1.y * w1.y + v1.z * w1.z + v1.w * w1.w
                        + v2.x * w2.x + v2.y * w2.y + v2.z * w2.z + v2.w * w2.w
                        + v3.x * w3.x + v3.y * w3.y + v3.z * w3.z + v3.w * w3.w;
            }
        }
    }
#pragma unroll
    for (int d = 0; d < 10; ++d) points[(size_t)n * 10 + d] = acc[d];
}

// ---------------------------------------------------------------------------
static constexpr int smem_sub(int CCH, int COUT, int TN) {
    return (CCH * COUT + TN * (CCH + 4) + 32) * (int)sizeof(float);
}

extern "C" void kernel_launch(void* const* d_in, const int* in_sizes, int n_in,
                              void* d_out, int out_size) {
    const float* feat1 = (const float*)d_in[0];
    const float* feat2 = (const float*)d_in[1];
    const float* feat3 = (const float*)d_in[2];
    const float* W1  = (const float*)d_in[3];
    const float* W1s = (const float*)d_in[4];
    const float* W2  = (const float*)d_in[5];
    const float* W2s = (const float*)d_in[6];
    const float* W3  = (const float*)d_in[7];
    const float* W3p = (const float*)d_in[8];
    const float* W3s = (const float*)d_in[9];
    const float* W3t = (const float*)d_in[10];
    const int* nbr1 = (const int*)d_in[11];
    const int* nbr2 = (const int*)d_in[12];
    const int* nbr3 = (const int*)d_in[13];
    const int* parent2 = (const int*)d_in[14];
    const int* parent3 = (const int*)d_in[15];
    const int* coords1 = (const int*)d_in[16];
    const int* coords2 = (const int*)d_in[17];

    const int N1 = in_sizes[0] / 80;
    const int N2 = in_sizes[1] / 48;
    const int N3 = in_sizes[2] / 16;

    float* out = (float*)d_out;
    float* points = out;
    float* ppn1  = points + (size_t)N3 * 10;
    float* ppn2  = ppn1 + (size_t)N1 * 6;
    float* mask1 = ppn2 + (size_t)N2 * 6;
    float* mask2 = mask1 + N1;

    float *y1, *y2, *z;
    cudaGetSymbolAddress((void**)&y1, g_y1);
    cudaGetSymbolAddress((void**)&y2, g_y2);
    cudaGetSymbolAddress((void**)&z, g_z);

    // --- Level 1 (coarse, 80ch): unchunked, TN=128, 68.6KB smem ---
    cudaFuncSetAttribute((const void*)subconv2<80, 80, 128, 4, 20, 4, 80>,
                         cudaFuncAttributeMaxDynamicSharedMemorySize,
                         smem_sub(80, 80, 128));
    subconv2<80, 80, 128, 4, 20, 4, 80>
        <<<(N1 + 127) / 128, 128, smem_sub(80, 80, 128)>>>(feat1, nbr1, W1, y1, N1);
    score_ppn_mask<80><<<(N1 + 255) / 256, 256>>>(y1, nbr1, W1s, coords1, ppn1, mask1, N1);

    // --- Level 2 (mid, 48ch): masked conv with per-stage skip ---
    subconv2m<48, 48, 128, 4, 12, 4>
        <<<(N2 + 127) / 128, 128, smem_sub(48, 48, 128)>>>(
            feat2, nbr2, W2, parent2, mask1, y2, N2);
    score_ppn_mask<48><<<(N2 + 255) / 256, 256>>>(y2, nbr2, W2s, coords2, ppn2, mask2, N2);

    // --- Level 3 (fine, 16ch): masked conv with per-stage skip ---
    subconv2m<16, 16, 256, 8, 4, 4>
        <<<(N3 + 255) / 256, 128, smem_sub(16, 16, 256)>>>(
            feat3, nbr3, W3, parent3, mask2, z, N3);
    heads_kernel<<<(N3 + 255) / 256, 256>>>(z, nbr3, W3p, W3s, W3t, points, N3);
}

// round 12
// speedup vs baseline: 1.2979x; 1.0040x over previous
#include <cuda_runtime.h>

// ---------------------------------------------------------------------------
// PPN on 3-level sparse voxel grid — FFMA2 convs + exact sparsity skips:
//   - masked convs skip all-zero-mask k-stages (R11-proven),
//   - masked convs emit per-row activity bytes (y2[n]==0 / z[n]==0 iff 0),
//   - score2/heads skip gathers of provably-zero rows (exact),
//   - L2 conv TN=256 amortizes W staging over 2x threads.
// output: points [N3,10] | ppn1 [N1,6] | ppn2 [N2,6] | mask1 [N1] | mask2 [N2]
// ---------------------------------------------------------------------------

#define N1_MAX 65536
#define N2_MAX 262144
#define N3_MAX 262144

__device__ float g_y1[(size_t)N1_MAX * 80];
__device__ float g_y2[(size_t)N2_MAX * 48];
__device__ float g_z[(size_t)N3_MAX * 16];
__device__ unsigned char g_act2[N2_MAX];
__device__ unsigned char g_act3[N3_MAX];

typedef unsigned long long ull;

__device__ __forceinline__ ull pk2(float x, float y) {
    ull r; asm("mov.b64 %0, {%1, %2};" : "=l"(r) : "f"(x), "f"(y)); return r;
}
__device__ __forceinline__ void fma2(ull& d, ull a, ull b) {
    asm("fma.rn.f32x2 %0, %1, %2, %0;" : "+l"(d) : "l"(a), "l"(b));
}
__device__ __forceinline__ float2 up2(ull v) {
    float a, b; asm("mov.b64 {%0, %1}, %2;" : "=f"(a), "=f"(b) : "l"(v));
    return make_float2(a, b);
}

// ---------------------------------------------------------------------------
// Unmasked conv (level 1) — R4/R9-proven cooperative-staging core.
// ---------------------------------------------------------------------------
template <int CIN, int COUT, int TN, int RN, int RD, int NTX, int CCH>
__global__ __launch_bounds__(128)
void subconv2(const float* __restrict__ feat, const int* __restrict__ nbr,
              const float* __restrict__ W, float* __restrict__ out, int N) {
    constexpr int CP = CCH + 4;
    constexpr int NTY = TN / RN;
    constexpr int NTH = NTX * NTY;
    static_assert(NTH == 128, "128 threads");
    static_assert(CIN % CCH == 0 && CCH % 4 == 0 && RD % 4 == 0, "");
    constexpr int NH = CIN / CCH;
    constexpr int VEC = CCH / 4;
    constexpr int NP = RD / 2;
    constexpr int NU = RD / 4;

    extern __shared__ float sh[];
    float* sW = sh;
    float* sF = sh + CCH * COUT;
    __shared__ int sIdx[TN];

    const int tid = threadIdx.x;
    const int tx = tid % NTX, ty = tid / NTX;
    const int n0 = blockIdx.x * TN;
    const int nb = ty * RN, db = tx * RD;

    ull acc[RN][NP];
#pragma unroll
    for (int i = 0; i < RN; ++i)
#pragma unroll
        for (int p = 0; p < NP; ++p) acc[i][p] = 0ULL;

    for (int k = 0; k < 27; ++k) {
        for (int i = tid; i < TN; i += NTH) {
            int n = n0 + i;
            sIdx[i] = (n < N) ? nbr[n * 27 + k] : N;
        }
        const float* Wk = W + (size_t)k * CIN * COUT;
#pragma unroll
        for (int h = 0; h < NH; ++h) {
            __syncthreads();
            for (int i = tid; i < CCH * COUT; i += NTH)
                sW[i] = Wk[h * CCH * COUT + i];
            const int bc = h * CCH;
            for (int i = tid; i < TN * VEC; i += NTH) {
                int n = i / VEC, c4 = (i - n * VEC) * 4;
                int idx = sIdx[n];
                float4 v = make_float4(0.f, 0.f, 0.f, 0.f);
                if ((unsigned)idx < (unsigned)N)
                    v = *reinterpret_cast<const float4*>(
                        feat + (size_t)idx * CIN + bc + c4);
                *reinterpret_cast<float4*>(sF + n * CP + c4) = v;
            }
            __syncthreads();

#pragma unroll
            for (int c4 = 0; c4 < CCH; c4 += 4) {
                float4 A[RN];
#pragma unroll
                for (int i = 0; i < RN; ++i)
                    A[i] = *reinterpret_cast<const float4*>(
                        sF + (nb + i) * CP + c4);
#pragma unroll
                for (int cc = 0; cc < 4; ++cc) {
                    ull as[RN];
#pragma unroll
                    for (int i = 0; i < RN; ++i) {
                        float v = (cc == 0) ? A[i].x : (cc == 1) ? A[i].y
                                 : (cc == 2) ? A[i].z : A[i].w;
                        as[i] = pk2(v, v);
                    }
                    const float* wrow = sW + (c4 + cc) * COUT + db;
#pragma unroll
                    for (int u = 0; u < NU; ++u) {
                        float4 B = *reinterpret_cast<const float4*>(wrow + 4 * u);
                        ull b0 = pk2(B.x, B.y), b1 = pk2(B.z, B.w);
#pragma unroll
                        for (int i = 0; i < RN; ++i) {
                            fma2(acc[i][2 * u], as[i], b0);
                            fma2(acc[i][2 * u + 1], as[i], b1);
                        }
                    }
                }
            }
        }
    }

#pragma unroll
    for (int i = 0; i < RN; ++i) {
        int n = n0 + nb + i;
        if (n < N) {
#pragma unroll
            for (int u = 0; u < NU; ++u) {
                float2 p0 = up2(acc[i][2 * u]), p1 = up2(acc[i][2 * u + 1]);
                float4 o = make_float4(p0.x, p0.y, p1.x, p1.y);
                *reinterpret_cast<float4*>(out + (size_t)n * COUT + db + 4 * u) = o;
            }
        }
    }
}

// ---------------------------------------------------------------------------
// Masked conv (levels 2/3): out[n,d] = sum_k sum_c mask[parent[j]]*feat[j,c]
// *W[k,c,d], j=nbr[n,k]. All-zero-mask k-stages are SKIPPED exactly; emits
// per-row activity byte act[n] = (out row may be nonzero).
// ---------------------------------------------------------------------------
template <int CIN, int COUT, int TN, int RN, int RD, int NTX>
__global__ __launch_bounds__(NTX*(TN/RN))
void subconv2m(const float* __restrict__ feat, const int* __restrict__ nbr,
               const float* __restrict__ W,
               const int* __restrict__ parent, const float* __restrict__ mask,
               float* __restrict__ out, unsigned char* __restrict__ act,
               int N) {
    constexpr int CP = CIN + 4;
    constexpr int NTY = TN / RN;
    constexpr int NTH = NTX * NTY;
    static_assert(NTH == 128 || NTH == 256, "thread count");
    static_assert(CIN % 4 == 0 && RD % 4 == 0 && TN % NTH == 0, "");
    constexpr int VEC = CIN / 4;
    constexpr int NP = RD / 2;
    constexpr int NU = RD / 4;
    constexpr int RPT = TN / NTH;        // rows tracked per thread

    extern __shared__ float sh[];
    float* sW = sh;                        // [CIN][COUT]
    float* sF = sh + CIN * COUT;           // [TN][CP]
    __shared__ int sIdx[TN];
    __shared__ float sM[TN];

    const int tid = threadIdx.x;
    const int tx = tid % NTX, ty = tid / NTX;
    const int n0 = blockIdx.x * TN;
    const int nb = ty * RN, db = tx * RD;

    ull acc[RN][NP];
#pragma unroll
    for (int i = 0; i < RN; ++i)
#pragma unroll
        for (int p = 0; p < NP; ++p) acc[i][p] = 0ULL;

    int rowAct[RPT];
#pragma unroll
    for (int j = 0; j < RPT; ++j) rowAct[j] = 0;

    for (int k = 0; k < 27; ++k) {
        // (A) stage indices + masks (disjoint from sW/sF still being read)
        int myAny = 0;
#pragma unroll
        for (int j = 0; j < RPT; ++j) {
            int i = tid + j * NTH;
            int n = n0 + i;
            int idx = (n < N) ? nbr[n * 27 + k] : N;
            float m = ((unsigned)idx < (unsigned)N) ? mask[parent[idx]] : 0.f;
            sIdx[i] = idx;
            sM[i] = m;
            int nz = (m != 0.f);
            myAny |= nz;
            rowAct[j] |= nz;
        }
        // barrier + block-OR; also orders prev compute before sF/sW rewrite
        if (!__syncthreads_or(myAny)) continue;   // exact: zero contribution

        const float* Wk = W + (size_t)k * CIN * COUT;
        for (int i = tid; i < CIN * COUT; i += NTH) sW[i] = Wk[i];
        for (int i = tid; i < TN * VEC; i += NTH) {
            int n = i / VEC, c4 = (i - n * VEC) * 4;
            int idx = sIdx[n];
            float4 v = make_float4(0.f, 0.f, 0.f, 0.f);
            if ((unsigned)idx < (unsigned)N) {
                float m = sM[n];
                if (m != 0.f) {
                    v = *reinterpret_cast<const float4*>(
                        feat + (size_t)idx * CIN + c4);
                    v.x *= m; v.y *= m; v.z *= m; v.w *= m;
                }
            }
            *reinterpret_cast<float4*>(sF + n * CP + c4) = v;
        }
        __syncthreads();

#pragma unroll
        for (int c4 = 0; c4 < CIN; c4 += 4) {
            float4 A[RN];
#pragma unroll
            for (int i = 0; i < RN; ++i)
                A[i] = *reinterpret_cast<const float4*>(sF + (nb + i) * CP + c4);
#pragma unroll
            for (int cc = 0; cc < 4; ++cc) {
                ull as[RN];
#pragma unroll
                for (int i = 0; i < RN; ++i) {
                    float v = (cc == 0) ? A[i].x : (cc == 1) ? A[i].y
                             : (cc == 2) ? A[i].z : A[i].w;
                    as[i] = pk2(v, v);
                }
                const float* wrow = sW + (c4 + cc) * COUT + db;
#pragma unroll
                for (int u = 0; u < NU; ++u) {
                    float4 B = *reinterpret_cast<const float4*>(wrow + 4 * u);
                    ull b0 = pk2(B.x, B.y), b1 = pk2(B.z, B.w);
#pragma unroll
                    for (int i = 0; i < RN; ++i) {
                        fma2(acc[i][2 * u], as[i], b0);
                        fma2(acc[i][2 * u + 1], as[i], b1);
                    }
                }
            }
        }
    }

    // write per-row activity (exact: row output is zero iff rowAct==0)
#pragma unroll
    for (int j = 0; j < RPT; ++j) {
        int n = n0 + tid + j * NTH;
        if (n < N) act[n] = (unsigned char)rowAct[j];
    }

#pragma unroll
    for (int i = 0; i < RN; ++i) {
        int n = n0 + nb + i;
        if (n < N) {
#pragma unroll
            for (int u = 0; u < NU; ++u) {
                float2 p0 = up2(acc[i][2 * u]), p1 = up2(acc[i][2 * u + 1]);
                float4 o = make_float4(p0.x, p0.y, p1.x, p1.y);
                *reinterpret_cast<float4*>(out + (size_t)n * COUT + db + 4 * u) = o;
            }
        }
    }
}

// ---------------------------------------------------------------------------
// Score head (Cout=2) + ppn concat + softmax-threshold mask. When ACT, rows
// with act[idx]==0 are exactly zero and their gather is skipped.
// softmax([s0,s1])[1] > 0.8  <=>  1/(1+exp(s0-s1)) > 0.8
// ---------------------------------------------------------------------------
template <int CIN, bool ACT>
__global__ void score_ppn_mask(const float* __restrict__ feat,
                               const int* __restrict__ nbr,
                               const float* __restrict__ Ws,
                               const int* __restrict__ coords,
                               const unsigned char* __restrict__ act,
                               float* __restrict__ ppn,
                               float* __restrict__ mask, int N) {
    __shared__ float sW[27 * 2 * CIN];  // [k][d][c]
    for (int i = threadIdx.x; i < 27 * CIN * 2; i += blockDim.x) {
        int k = i / (CIN * 2);
        int r = i - k * (CIN * 2);
        int c = r >> 1, d = r & 1;
        sW[(k * 2 + d) * CIN + c] = Ws[i];
    }
    __syncthreads();
    int n = blockIdx.x * blockDim.x + threadIdx.x;
    if (n >= N) return;

    float a0 = 0.f, a1 = 0.f;
    for (int k = 0; k < 27; ++k) {
        int idx = nbr[n * 27 + k];
        if ((unsigned)idx < (unsigned)N) {
            if (ACT && !act[idx]) continue;   // row exactly zero
            const float4* fr = reinterpret_cast<const float4*>(feat + (size_t)idx * CIN);
            const float4* w0 = reinterpret_cast<const float4*>(sW + (k * 2 + 0) * CIN);
            const float4* w1 = reinterpret_cast<const float4*>(sW + (k * 2 + 1) * CIN);
#pragma unroll
            for (int j = 0; j < CIN / 4; ++j) {
                float4 v = fr[j], x = w0[j], y = w1[j];
                a0 += v.x * x.x + v.y * x.y + v.z * x.z + v.w * x.w;
                a1 += v.x * y.x + v.y * y.y + v.z * y.z + v.w * y.w;
            }
        }
    }
    ppn[(size_t)n * 6 + 0] = (float)coords[n * 4 + 0];
    ppn[(size_t)n * 6 + 1] = (float)coords[n * 4 + 1];
    ppn[(size_t)n * 6 + 2] = (float)coords[n * 4 + 2];
    ppn[(size_t)n * 6 + 3] = (float)coords[n * 4 + 3];
    ppn[(size_t)n * 6 + 4] = a0;
    ppn[(size_t)n * 6 + 5] = a1;
    float p = 1.f / (1.f + expf(a0 - a1));
    mask[n] = (p > 0.8f) ? 1.f : 0.f;
}

// Fine heads fused: points[n, 0:3|3:5|5:10]; skips exactly-zero z rows.
__global__ void heads_kernel(const float* __restrict__ z,
                             const int* __restrict__ nbr,
                             const float* __restrict__ Wp,
                             const float* __restrict__ Wsc,
                             const float* __restrict__ Wt,
                             const unsigned char* __restrict__ act,
                             float* __restrict__ points, int N) {
    __shared__ float sW[27 * 10 * 16];  // [k][d][c]
    for (int i = threadIdx.x; i < 27 * 16 * 3; i += blockDim.x) {
        int k = i / 48; int r = i - k * 48; int c = r / 3; int d = r - c * 3;
        sW[(k * 10 + d) * 16 + c] = Wp[i];
    }
    for (int i = threadIdx.x; i < 27 * 16 * 2; i += blockDim.x) {
        int k = i / 32; int r = i - k * 32; int c = r >> 1; int d = r & 1;
        sW[(k * 10 + 3 + d) * 16 + c] = Wsc[i];
    }
    for (int i = threadIdx.x; i < 27 * 16 * 5; i += blockDim.x) {
        int k = i / 80; int r = i - k * 80; int c = r / 5; int d = r - c * 5;
        sW[(k * 10 + 5 + d) * 16 + c] = Wt[i];
    }
    __syncthreads();
    int n = blockIdx.x * blockDim.x + threadIdx.x;
    if (n >= N) return;

    float acc[10];
#pragma unroll
    for (int d = 0; d < 10; ++d) acc[d] = 0.f;

    for (int k = 0; k < 27; ++k) {
        int idx = nbr[n * 27 + k];
        if ((unsigned)idx < (unsigned)N && act[idx]) {
            const float4* zr = reinterpret_cast<const float4*>(z + (size_t)idx * 16);
            float4 v0 = zr[0], v1 = zr[1], v2 = zr[2], v3 = zr[3];
#pragma unroll
            for (int d = 0; d < 10; ++d) {
                const float4* wr = reinterpret_cast<const float4*>(sW + (k * 10 + d) * 16);
                float4 w0 = wr[0], w1 = wr[1], w2 = wr[2], w3 = wr[3];
                acc[d] += v0.x * w0.x + v0.y * w0.y + v0.z * w0.z + v0.w * w0.w
                        + v1.x * w1.x + v1.y * w1.y + v1.z * w1.z + v1.w * w1.w
                        + v2.x * w2.x + v2.y * w2.y + v2.z * w2.z + v2.w * w2.w
                        + v3.x * w3.x + v3.y * w3.y + v3.z * w3.z + v3.w * w3.w;
            }
        }
    }
#pragma unroll
    for (int d = 0; d < 10; ++d) points[(size_t)n * 10 + d] = acc[d];
}

// ---------------------------------------------------------------------------
static constexpr int smem_sub(int CCH, int COUT, int TN) {
    return (CCH * COUT + TN * (CCH + 4) + 32) * (int)sizeof(float);
}

extern "C" void kernel_launch(void* const* d_in, const int* in_sizes, int n_in,
                              void* d_out, int out_size) {
    const float* feat1 = (const float*)d_in[0];
    const float* feat2 = (const float*)d_in[1];
    const float* feat3 = (const float*)d_in[2];
    const float* W1  = (const float*)d_in[3];
    const float* W1s = (const float*)d_in[4];
    const float* W2  = (const float*)d_in[5];
    const float* W2s = (const float*)d_in[6];
    const float* W3  = (const float*)d_in[7];
    const float* W3p = (const float*)d_in[8];
    const float* W3s = (const float*)d_in[9];
    const float* W3t = (const float*)d_in[10];
    const int* nbr1 = (const int*)d_in[11];
    const int* nbr2 = (const int*)d_in[12];
    const int* nbr3 = (const int*)d_in[13];
    const int* parent2 = (const int*)d_in[14];
    const int* parent3 = (const int*)d_in[15];
    const int* coords1 = (const int*)d_in[16];
    const int* coords2 = (const int*)d_in[17];

    const int N1 = in_sizes[0] / 80;
    const int N2 = in_sizes[1] / 48;
    const int N3 = in_sizes[2] / 16;

    float* out = (float*)d_out;
    float* points = out;
    float* ppn1  = points + (size_t)N3 * 10;
    float* ppn2  = ppn1 + (size_t)N1 * 6;
    float* mask1 = ppn2 + (size_t)N2 * 6;
    float* mask2 = mask1 + N1;

    float *y1, *y2, *z;
    unsigned char *act2, *act3;
    cudaGetSymbolAddress((void**)&y1, g_y1);
    cudaGetSymbolAddress((void**)&y2, g_y2);
    cudaGetSymbolAddress((void**)&z, g_z);
    cudaGetSymbolAddress((void**)&act2, g_act2);
    cudaGetSymbolAddress((void**)&act3, g_act3);

    // --- Level 1 (coarse, 80ch): unchunked, TN=128, 68.6KB smem ---
    cudaFuncSetAttribute((const void*)subconv2<80, 80, 128, 4, 20, 4, 80>,
                         cudaFuncAttributeMaxDynamicSharedMemorySize,
                         smem_sub(80, 80, 128));
    subconv2<80, 80, 128, 4, 20, 4, 80>
        <<<(N1 + 127) / 128, 128, smem_sub(80, 80, 128)>>>(feat1, nbr1, W1, y1, N1);
    score_ppn_mask<80, false><<<(N1 + 255) / 256, 256>>>(
        y1, nbr1, W1s, coords1, nullptr, ppn1, mask1, N1);

    // --- Level 2 (mid, 48ch): masked conv, TN=256 (90KB smem), act flags ---
    cudaFuncSetAttribute((const void*)subconv2m<48, 48, 256, 4, 12, 4>,
                         cudaFuncAttributeMaxDynamicSharedMemorySize,
                         smem_sub(48, 48, 256));
    subconv2m<48, 48, 256, 4, 12, 4>
        <<<(N2 + 255) / 256, 256, smem_sub(48, 48, 256)>>>(
            feat2, nbr2, W2, parent2, mask1, y2, act2, N2);
    score_ppn_mask<48, true><<<(N2 + 255) / 256, 256>>>(
        y2, nbr2, W2s, coords2, act2, ppn2, mask2, N2);

    // --- Level 3 (fine, 16ch): masked conv with skip + act flags ---
    subconv2m<16, 16, 256, 8, 4, 4>
        <<<(N3 + 255) / 256, 128, smem_sub(16, 16, 256)>>>(
            feat3, nbr3, W3, parent3, mask2, z, act3, N3);
    heads_kernel<<<(N3 + 255) / 256, 256>>>(
        z, nbr3, W3p, W3s, W3t, act3, points, N3);
}

// round 13
// speedup vs baseline: 1.3240x; 1.0201x over previous
#include <cuda_runtime.h>

// ---------------------------------------------------------------------------
// PPN on 3-level sparse voxel grid — FFMA2 convs + exact sparsity skips.
// This round: same proven microtiles, +occupancy via launch_bounds minBlocks
// (L2: 5 blocks/SM target) and L1 chunked CCH=40 (35KB smem -> 4 blocks/SM).
// output: points [N3,10] | ppn1 [N1,6] | ppn2 [N2,6] | mask1 [N1] | mask2 [N2]
// ---------------------------------------------------------------------------

#define N1_MAX 65536
#define N2_MAX 262144
#define N3_MAX 262144

__device__ float g_y1[(size_t)N1_MAX * 80];
__device__ float g_y2[(size_t)N2_MAX * 48];
__device__ float g_z[(size_t)N3_MAX * 16];
__device__ unsigned char g_act2[N2_MAX];
__device__ unsigned char g_act3[N3_MAX];

typedef unsigned long long ull;

__device__ __forceinline__ ull pk2(float x, float y) {
    ull r; asm("mov.b64 %0, {%1, %2};" : "=l"(r) : "f"(x), "f"(y)); return r;
}
__device__ __forceinline__ void fma2(ull& d, ull a, ull b) {
    asm("fma.rn.f32x2 %0, %1, %2, %0;" : "+l"(d) : "l"(a), "l"(b));
}
__device__ __forceinline__ float2 up2(ull v) {
    float a, b; asm("mov.b64 {%0, %1}, %2;" : "=f"(a), "=f"(b) : "l"(v));
    return make_float2(a, b);
}

// ---------------------------------------------------------------------------
// Unmasked conv (level 1) — cooperative staging per (k, CIN-chunk).
// ---------------------------------------------------------------------------
template <int CIN, int COUT, int TN, int RN, int RD, int NTX, int CCH, int MINB>
__global__ __launch_bounds__(NTX*(TN/RN), MINB)
void subconv2(const float* __restrict__ feat, const int* __restrict__ nbr,
              const float* __restrict__ W, float* __restrict__ out, int N) {
    constexpr int CP = CCH + 4;
    constexpr int NTY = TN / RN;
    constexpr int NTH = NTX * NTY;
    static_assert(NTH == 128, "128 threads");
    static_assert(CIN % CCH == 0 && CCH % 4 == 0 && RD % 4 == 0, "");
    constexpr int NH = CIN / CCH;
    constexpr int VEC = CCH / 4;
    constexpr int NP = RD / 2;
    constexpr int NU = RD / 4;

    extern __shared__ float sh[];
    float* sW = sh;
    float* sF = sh + CCH * COUT;
    __shared__ int sIdx[TN];

    const int tid = threadIdx.x;
    const int tx = tid % NTX, ty = tid / NTX;
    const int n0 = blockIdx.x * TN;
    const int nb = ty * RN, db = tx * RD;

    ull acc[RN][NP];
#pragma unroll
    for (int i = 0; i < RN; ++i)
#pragma unroll
        for (int p = 0; p < NP; ++p) acc[i][p] = 0ULL;

    for (int k = 0; k < 27; ++k) {
        for (int i = tid; i < TN; i += NTH) {
            int n = n0 + i;
            sIdx[i] = (n < N) ? nbr[n * 27 + k] : N;
        }
        const float* Wk = W + (size_t)k * CIN * COUT;
#pragma unroll
        for (int h = 0; h < NH; ++h) {
            __syncthreads();
            for (int i = tid; i < CCH * COUT; i += NTH)
                sW[i] = Wk[h * CCH * COUT + i];
            const int bc = h * CCH;
            for (int i = tid; i < TN * VEC; i += NTH) {
                int n = i / VEC, c4 = (i - n * VEC) * 4;
                int idx = sIdx[n];
                float4 v = make_float4(0.f, 0.f, 0.f, 0.f);
                if ((unsigned)idx < (unsigned)N)
                    v = *reinterpret_cast<const float4*>(
                        feat + (size_t)idx * CIN + bc + c4);
                *reinterpret_cast<float4*>(sF + n * CP + c4) = v;
            }
            __syncthreads();

#pragma unroll
            for (int c4 = 0; c4 < CCH; c4 += 4) {
                float4 A[RN];
#pragma unroll
                for (int i = 0; i < RN; ++i)
                    A[i] = *reinterpret_cast<const float4*>(
                        sF + (nb + i) * CP + c4);
#pragma unroll
                for (int cc = 0; cc < 4; ++cc) {
                    ull as[RN];
#pragma unroll
                    for (int i = 0; i < RN; ++i) {
                        float v = (cc == 0) ? A[i].x : (cc == 1) ? A[i].y
                                 : (cc == 2) ? A[i].z : A[i].w;
                        as[i] = pk2(v, v);
                    }
                    const float* wrow = sW + (c4 + cc) * COUT + db;
#pragma unroll
                    for (int u = 0; u < NU; ++u) {
                        float4 B = *reinterpret_cast<const float4*>(wrow + 4 * u);
                        ull b0 = pk2(B.x, B.y), b1 = pk2(B.z, B.w);
#pragma unroll
                        for (int i = 0; i < RN; ++i) {
                            fma2(acc[i][2 * u], as[i], b0);
                            fma2(acc[i][2 * u + 1], as[i], b1);
                        }
                    }
                }
            }
        }
    }

#pragma unroll
    for (int i = 0; i < RN; ++i) {
        int n = n0 + nb + i;
        if (n < N) {
#pragma unroll
            for (int u = 0; u < NU; ++u) {
                float2 p0 = up2(acc[i][2 * u]), p1 = up2(acc[i][2 * u + 1]);
                float4 o = make_float4(p0.x, p0.y, p1.x, p1.y);
                *reinterpret_cast<float4*>(out + (size_t)n * COUT + db + 4 * u) = o;
            }
        }
    }
}

// ---------------------------------------------------------------------------
// Masked conv (levels 2/3): out[n,d] = sum_k sum_c mask[parent[j]]*feat[j,c]
// *W[k,c,d], j=nbr[n,k]. All-zero-mask k-stages SKIPPED exactly; emits
// per-row activity byte act[n].
// ---------------------------------------------------------------------------
template <int CIN, int COUT, int TN, int RN, int RD, int NTX, int MINB>
__global__ __launch_bounds__(NTX*(TN/RN), MINB)
void subconv2m(const float* __restrict__ feat, const int* __restrict__ nbr,
               const float* __restrict__ W,
               const int* __restrict__ parent, const float* __restrict__ mask,
               float* __restrict__ out, unsigned char* __restrict__ act,
               int N) {
    constexpr int CP = CIN + 4;
    constexpr int NTY = TN / RN;
    constexpr int NTH = NTX * NTY;
    static_assert(NTH == 128 || NTH == 256, "thread count");
    static_assert(CIN % 4 == 0 && RD % 4 == 0 && TN % NTH == 0, "");
    constexpr int VEC = CIN / 4;
    constexpr int NP = RD / 2;
    constexpr int NU = RD / 4;
    constexpr int RPT = TN / NTH;

    extern __shared__ float sh[];
    float* sW = sh;                        // [CIN][COUT]
    float* sF = sh + CIN * COUT;           // [TN][CP]
    __shared__ int sIdx[TN];
    __shared__ float sM[TN];

    const int tid = threadIdx.x;
    const int tx = tid % NTX, ty = tid / NTX;
    const int n0 = blockIdx.x * TN;
    const int nb = ty * RN, db = tx * RD;

    ull acc[RN][NP];
#pragma unroll
    for (int i = 0; i < RN; ++i)
#pragma unroll
        for (int p = 0; p < NP; ++p) acc[i][p] = 0ULL;

    int rowAct[RPT];
#pragma unroll
    for (int j = 0; j < RPT; ++j) rowAct[j] = 0;

    for (int k = 0; k < 27; ++k) {
        int myAny = 0;
#pragma unroll
        for (int j = 0; j < RPT; ++j) {
            int i = tid + j * NTH;
            int n = n0 + i;
            int idx = (n < N) ? nbr[n * 27 + k] : N;
            float m = ((unsigned)idx < (unsigned)N) ? mask[parent[idx]] : 0.f;
            sIdx[i] = idx;
            sM[i] = m;
            int nz = (m != 0.f);
            myAny |= nz;
            rowAct[j] |= nz;
        }
        if (!__syncthreads_or(myAny)) continue;   // exact: zero contribution

        const float* Wk = W + (size_t)k * CIN * COUT;
        for (int i = tid; i < CIN * COUT; i += NTH) sW[i] = Wk[i];
        for (int i = tid; i < TN * VEC; i += NTH) {
            int n = i / VEC, c4 = (i - n * VEC) * 4;
            int idx = sIdx[n];
            float4 v = make_float4(0.f, 0.f, 0.f, 0.f);
            if ((unsigned)idx < (unsigned)N) {
                float m = sM[n];
                if (m != 0.f) {
                    v = *reinterpret_cast<const float4*>(
                        feat + (size_t)idx * CIN + c4);
                    v.x *= m; v.y *= m; v.z *= m; v.w *= m;
                }
            }
            *reinterpret_cast<float4*>(sF + n * CP + c4) = v;
        }
        __syncthreads();

#pragma unroll
        for (int c4 = 0; c4 < CIN; c4 += 4) {
            float4 A[RN];
#pragma unroll
            for (int i = 0; i < RN; ++i)
                A[i] = *reinterpret_cast<const float4*>(sF + (nb + i) * CP + c4);
#pragma unroll
            for (int cc = 0; cc < 4; ++cc) {
                ull as[RN];
#pragma unroll
                for (int i = 0; i < RN; ++i) {
                    float v = (cc == 0) ? A[i].x : (cc == 1) ? A[i].y
                             : (cc == 2) ? A[i].z : A[i].w;
                    as[i] = pk2(v, v);
                }
                const float* wrow = sW + (c4 + cc) * COUT + db;
#pragma unroll
                for (int u = 0; u < NU; ++u) {
                    float4 B = *reinterpret_cast<const float4*>(wrow + 4 * u);
                    ull b0 = pk2(B.x, B.y), b1 = pk2(B.z, B.w);
#pragma unroll
                    for (int i = 0; i < RN; ++i) {
                        fma2(acc[i][2 * u], as[i], b0);
                        fma2(acc[i][2 * u + 1], as[i], b1);
                    }
                }
            }
        }
    }

#pragma unroll
    for (int j = 0; j < RPT; ++j) {
        int n = n0 + tid + j * NTH;
        if (n < N) act[n] = (unsigned char)rowAct[j];
    }

#pragma unroll
    for (int i = 0; i < RN; ++i) {
        int n = n0 + nb + i;
        if (n < N) {
#pragma unroll
            for (int u = 0; u < NU; ++u) {
                float2 p0 = up2(acc[i][2 * u]), p1 = up2(acc[i][2 * u + 1]);
                float4 o = make_float4(p0.x, p0.y, p1.x, p1.y);
                *reinterpret_cast<float4*>(out + (size_t)n * COUT + db + 4 * u) = o;
            }
        }
    }
}

// ---------------------------------------------------------------------------
// Score head (Cout=2) + ppn concat + softmax-threshold mask. When ACT, rows
// with act[idx]==0 are exactly zero and their gather is skipped.
// softmax([s0,s1])[1] > 0.8  <=>  1/(1+exp(s0-s1)) > 0.8
// ---------------------------------------------------------------------------
template <int CIN, bool ACT>
__global__ void score_ppn_mask(const float* __restrict__ feat,
                               const int* __restrict__ nbr,
                               const float* __restrict__ Ws,
                               const int* __restrict__ coords,
                               const unsigned char* __restrict__ act,
                               float* __restrict__ ppn,
                               float* __restrict__ mask, int N) {
    __shared__ float sW[27 * 2 * CIN];  // [k][d][c]
    for (int i = threadIdx.x; i < 27 * CIN * 2; i += blockDim.x) {
        int k = i / (CIN * 2);
        int r = i - k * (CIN * 2);
        int c = r >> 1, d = r & 1;
        sW[(k * 2 + d) * CIN + c] = Ws[i];
    }
    __syncthreads();
    int n = blockIdx.x * blockDim.x + threadIdx.x;
    if (n >= N) return;

    float a0 = 0.f, a1 = 0.f;
    for (int k = 0; k < 27; ++k) {
        int idx = nbr[n * 27 + k];
        if ((unsigned)idx < (unsigned)N) {
            if (ACT && !act[idx]) continue;   // row exactly zero
            const float4* fr = reinterpret_cast<const float4*>(feat + (size_t)idx * CIN);
            const float4* w0 = reinterpret_cast<const float4*>(sW + (k * 2 + 0) * CIN);
            const float4* w1 = reinterpret_cast<const float4*>(sW + (k * 2 + 1) * CIN);
#pragma unroll
            for (int j = 0; j < CIN / 4; ++j) {
                float4 v = fr[j], x = w0[j], y = w1[j];
                a0 += v.x * x.x + v.y * x.y + v.z * x.z + v.w * x.w;
                a1 += v.x * y.x + v.y * y.y + v.z * y.z + v.w * y.w;
            }
        }
    }
    ppn[(size_t)n * 6 + 0] = (float)coords[n * 4 + 0];
    ppn[(size_t)n * 6 + 1] = (float)coords[n * 4 + 1];
    ppn[(size_t)n * 6 + 2] = (float)coords[n * 4 + 2];
    ppn[(size_t)n * 6 + 3] = (float)coords[n * 4 + 3];
    ppn[(size_t)n * 6 + 4] = a0;
    ppn[(size_t)n * 6 + 5] = a1;
    float p = 1.f / (1.f + expf(a0 - a1));
    mask[n] = (p > 0.8f) ? 1.f : 0.f;
}

// Fine heads fused: points[n, 0:3|3:5|5:10]; skips exactly-zero z rows.
__global__ void heads_kernel(const float* __restrict__ z,
                             const int* __restrict__ nbr,
                             const float* __restrict__ Wp,
                             const float* __restrict__ Wsc,
                             const float* __restrict__ Wt,
                             const unsigned char* __restrict__ act,
                             float* __restrict__ points, int N) {
    __shared__ float sW[27 * 10 * 16];  // [k][d][c]
    for (int i = threadIdx.x; i < 27 * 16 * 3; i += blockDim.x) {
        int k = i / 48; int r = i - k * 48; int c = r / 3; int d = r - c * 3;
        sW[(k * 10 + d) * 16 + c] = Wp[i];
    }
    for (int i = threadIdx.x; i < 27 * 16 * 2; i += blockDim.x) {
        int k = i / 32; int r = i - k * 32; int c = r >> 1; int d = r & 1;
        sW[(k * 10 + 3 + d) * 16 + c] = Wsc[i];
    }
    for (int i = threadIdx.x; i < 27 * 16 * 5; i += blockDim.x) {
        int k = i / 80; int r = i - k * 80; int c = r / 5; int d = r - c * 5;
        sW[(k * 10 + 5 + d) * 16 + c] = Wt[i];
    }
    __syncthreads();
    int n = blockIdx.x * blockDim.x + threadIdx.x;
    if (n >= N) return;

    float acc[10];
#pragma unroll
    for (int d = 0; d < 10; ++d) acc[d] = 0.f;

    for (int k = 0; k < 27; ++k) {
        int idx = nbr[n * 27 + k];
        if ((unsigned)idx < (unsigned)N && act[idx]) {
            const float4* zr = reinterpret_cast<const float4*>(z + (size_t)idx * 16);
            float4 v0 = zr[0], v1 = zr[1], v2 = zr[2], v3 = zr[3];
#pragma unroll
            for (int d = 0; d < 10; ++d) {
                const float4* wr = reinterpret_cast<const float4*>(sW + (k * 10 + d) * 16);
                float4 w0 = wr[0], w1 = wr[1], w2 = wr[2], w3 = wr[3];
                acc[d] += v0.x * w0.x + v0.y * w0.y + v0.z * w0.z + v0.w * w0.w
                        + v1.x * w1.x + v1.y * w1.y + v1.z * w1.z + v1.w * w1.w
                        + v2.x * w2.x + v2.y * w2.y + v2.z * w2.z + v2.w * w2.w
                        + v3.x * w3.x + v3.y * w3.y + v3.z * w3.z + v3.w * w3.w;
            }
        }
    }
#pragma unroll
    for (int d = 0; d < 10; ++d) points[(size_t)n * 10 + d] = acc[d];
}

// ---------------------------------------------------------------------------
static constexpr int smem_sub(int CCH, int COUT, int TN) {
    return (CCH * COUT + TN * (CCH + 4) + 32) * (int)sizeof(float);
}

extern "C" void kernel_launch(void* const* d_in, const int* in_sizes, int n_in,
                              void* d_out, int out_size) {
    const float* feat1 = (const float*)d_in[0];
    const float* feat2 = (const float*)d_in[1];
    const float* feat3 = (const float*)d_in[2];
    const float* W1  = (const float*)d_in[3];
    const float* W1s = (const float*)d_in[4];
    const float* W2  = (const float*)d_in[5];
    const float* W2s = (const float*)d_in[6];
    const float* W3  = (const float*)d_in[7];
    const float* W3p = (const float*)d_in[8];
    const float* W3s = (const float*)d_in[9];
    const float* W3t = (const float*)d_in[10];
    const int* nbr1 = (const int*)d_in[11];
    const int* nbr2 = (const int*)d_in[12];
    const int* nbr3 = (const int*)d_in[13];
    const int* parent2 = (const int*)d_in[14];
    const int* parent3 = (const int*)d_in[15];
    const int* coords1 = (const int*)d_in[16];
    const int* coords2 = (const int*)d_in[17];

    const int N1 = in_sizes[0] / 80;
    const int N2 = in_sizes[1] / 48;
    const int N3 = in_sizes[2] / 16;

    float* out = (float*)d_out;
    float* points = out;
    float* ppn1  = points + (size_t)N3 * 10;
    float* ppn2  = ppn1 + (size_t)N1 * 6;
    float* mask1 = ppn2 + (size_t)N2 * 6;
    float* mask2 = mask1 + N1;

    float *y1, *y2, *z;
    unsigned char *act2, *act3;
    cudaGetSymbolAddress((void**)&y1, g_y1);
    cudaGetSymbolAddress((void**)&y2, g_y2);
    cudaGetSymbolAddress((void**)&z, g_z);
    cudaGetSymbolAddress((void**)&act2, g_act2);
    cudaGetSymbolAddress((void**)&act3, g_act3);

    // --- Level 1 (coarse, 80ch): chunked CCH=40, 35.4KB smem, 4 blk/SM ---
    subconv2<80, 80, 128, 4, 20, 4, 40, 4>
        <<<(N1 + 127) / 128, 128, smem_sub(40, 80, 128)>>>(feat1, nbr1, W1, y1, N1);
    score_ppn_mask<80, false><<<(N1 + 255) / 256, 256>>>(
        y1, nbr1, W1s, coords1, nullptr, ppn1, mask1, N1);

    // --- Level 2 (mid, 48ch): proven TN=128 conv + minBlocks=5 ---
    subconv2m<48, 48, 128, 4, 12, 4, 5>
        <<<(N2 + 127) / 128, 128, smem_sub(48, 48, 128)>>>(
            feat2, nbr2, W2, parent2, mask1, y2, act2, N2);
    score_ppn_mask<48, true><<<(N2 + 255) / 256, 256>>>(
        y2, nbr2, W2s, coords2, act2, ppn2, mask2, N2);

    // --- Level 3 (fine, 16ch): masked conv with skip + act flags ---
    subconv2m<16, 16, 256, 8, 4, 4, 1>
        <<<(N3 + 255) / 256, 128, smem_sub(16, 16, 256)>>>(
            feat3, nbr3, W3, parent3, mask2, z, act3, N3);
    heads_kernel<<<(N3 + 255) / 256, 256>>>(
        z, nbr3, W3p, W3s, W3t, act3, points, N3);
}

// round 14
// speedup vs baseline: 1.3307x; 1.0051x over previous
#include <cuda_runtime.h>

// ---------------------------------------------------------------------------
// PPN on 3-level sparse voxel grid — FFMA2 convs + exact sparsity skips.
// R14: (1) batched pointer-chase in score/heads (27 idx + 27 act preloaded
// into regs for MLP), (2) pm[j]=mask[parent[j]] precomputed per level so
// masked-conv staging is a single indirection.
// output: points [N3,10] | ppn1 [N1,6] | ppn2 [N2,6] | mask1 [N1] | mask2 [N2]
// ---------------------------------------------------------------------------

#define N1_MAX 65536
#define N2_MAX 262144
#define N3_MAX 262144

__device__ float g_y1[(size_t)N1_MAX * 80];
__device__ float g_y2[(size_t)N2_MAX * 48];
__device__ float g_z[(size_t)N3_MAX * 16];
__device__ float g_pm2[N2_MAX];
__device__ float g_pm3[N3_MAX];
__device__ unsigned char g_act2[N2_MAX];
__device__ unsigned char g_act3[N3_MAX];

typedef unsigned long long ull;

__device__ __forceinline__ ull pk2(float x, float y) {
    ull r; asm("mov.b64 %0, {%1, %2};" : "=l"(r) : "f"(x), "f"(y)); return r;
}
__device__ __forceinline__ void fma2(ull& d, ull a, ull b) {
    asm("fma.rn.f32x2 %0, %1, %2, %0;" : "+l"(d) : "l"(a), "l"(b));
}
__device__ __forceinline__ float2 up2(ull v) {
    float a, b; asm("mov.b64 {%0, %1}, %2;" : "=f"(a), "=f"(b) : "l"(v));
    return make_float2(a, b);
}

// pm[i] = mask[parent[i]]
__global__ void premask(const int* __restrict__ parent,
                        const float* __restrict__ mask,
                        float* __restrict__ pm, int N) {
    int i = blockIdx.x * blockDim.x + threadIdx.x;
    if (i < N) pm[i] = mask[parent[i]];
}

// ---------------------------------------------------------------------------
// Unmasked conv (level 1) — cooperative staging per (k, CIN-chunk).
// ---------------------------------------------------------------------------
template <int CIN, int COUT, int TN, int RN, int RD, int NTX, int CCH, int MINB>
__global__ __launch_bounds__(NTX*(TN/RN), MINB)
void subconv2(const float* __restrict__ feat, const int* __restrict__ nbr,
              const float* __restrict__ W, float* __restrict__ out, int N) {
    constexpr int CP = CCH + 4;
    constexpr int NTY = TN / RN;
    constexpr int NTH = NTX * NTY;
    static_assert(NTH == 128, "128 threads");
    static_assert(CIN % CCH == 0 && CCH % 4 == 0 && RD % 4 == 0, "");
    constexpr int NH = CIN / CCH;
    constexpr int VEC = CCH / 4;
    constexpr int NP = RD / 2;
    constexpr int NU = RD / 4;

    extern __shared__ float sh[];
    float* sW = sh;
    float* sF = sh + CCH * COUT;
    __shared__ int sIdx[TN];

    const int tid = threadIdx.x;
    const int tx = tid % NTX, ty = tid / NTX;
    const int n0 = blockIdx.x * TN;
    const int nb = ty * RN, db = tx * RD;

    ull acc[RN][NP];
#pragma unroll
    for (int i = 0; i < RN; ++i)
#pragma unroll
        for (int p = 0; p < NP; ++p) acc[i][p] = 0ULL;

    for (int k = 0; k < 27; ++k) {
        for (int i = tid; i < TN; i += NTH) {
            int n = n0 + i;
            sIdx[i] = (n < N) ? nbr[n * 27 + k] : N;
        }
        const float* Wk = W + (size_t)k * CIN * COUT;
#pragma unroll
        for (int h = 0; h < NH; ++h) {
            __syncthreads();
            for (int i = tid; i < CCH * COUT; i += NTH)
                sW[i] = Wk[h * CCH * COUT + i];
            const int bc = h * CCH;
            for (int i = tid; i < TN * VEC; i += NTH) {
                int n = i / VEC, c4 = (i - n * VEC) * 4;
                int idx = sIdx[n];
                float4 v = make_float4(0.f, 0.f, 0.f, 0.f);
                if ((unsigned)idx < (unsigned)N)
                    v = *reinterpret_cast<const float4*>(
                        feat + (size_t)idx * CIN + bc + c4);
                *reinterpret_cast<float4*>(sF + n * CP + c4) = v;
            }
            __syncthreads();

#pragma unroll
            for (int c4 = 0; c4 < CCH; c4 += 4) {
                float4 A[RN];
#pragma unroll
                for (int i = 0; i < RN; ++i)
                    A[i] = *reinterpret_cast<const float4*>(
                        sF + (nb + i) * CP + c4);
#pragma unroll
                for (int cc = 0; cc < 4; ++cc) {
                    ull as[RN];
#pragma unroll
                    for (int i = 0; i < RN; ++i) {
                        float v = (cc == 0) ? A[i].x : (cc == 1) ? A[i].y
                                 : (cc == 2) ? A[i].z : A[i].w;
                        as[i] = pk2(v, v);
                    }
                    const float* wrow = sW + (c4 + cc) * COUT + db;
#pragma unroll
                    for (int u = 0; u < NU; ++u) {
                        float4 B = *reinterpret_cast<const float4*>(wrow + 4 * u);
                        ull b0 = pk2(B.x, B.y), b1 = pk2(B.z, B.w);
#pragma unroll
                        for (int i = 0; i < RN; ++i) {
                            fma2(acc[i][2 * u], as[i], b0);
                            fma2(acc[i][2 * u + 1], as[i], b1);
                        }
                    }
                }
            }
        }
    }

#pragma unroll
    for (int i = 0; i < RN; ++i) {
        int n = n0 + nb + i;
        if (n < N) {
#pragma unroll
            for (int u = 0; u < NU; ++u) {
                float2 p0 = up2(acc[i][2 * u]), p1 = up2(acc[i][2 * u + 1]);
                float4 o = make_float4(p0.x, p0.y, p1.x, p1.y);
                *reinterpret_cast<float4*>(out + (size_t)n * COUT + db + 4 * u) = o;
            }
        }
    }
}

// ---------------------------------------------------------------------------
// Masked conv (levels 2/3): out[n,d] = sum_k sum_c pm[j]*feat[j,c]*W[k,c,d],
// j=nbr[n,k], pm precomputed. All-zero-mask k-stages SKIPPED exactly;
// emits per-row activity byte act[n].
// ---------------------------------------------------------------------------
template <int CIN, int COUT, int TN, int RN, int RD, int NTX, int MINB>
__global__ __launch_bounds__(NTX*(TN/RN), MINB)
void subconv2m(const float* __restrict__ feat, const int* __restrict__ nbr,
               const float* __restrict__ W, const float* __restrict__ pm,
               float* __restrict__ out, unsigned char* __restrict__ act,
               int N) {
    constexpr int CP = CIN + 4;
    constexpr int NTY = TN / RN;
    constexpr int NTH = NTX * NTY;
    static_assert(NTH == 128 || NTH == 256, "thread count");
    static_assert(CIN % 4 == 0 && RD % 4 == 0 && TN % NTH == 0, "");
    constexpr int VEC = CIN / 4;
    constexpr int NP = RD / 2;
    constexpr int NU = RD / 4;
    constexpr int RPT = TN / NTH;

    extern __shared__ float sh[];
    float* sW = sh;                        // [CIN][COUT]
    float* sF = sh + CIN * COUT;           // [TN][CP]
    __shared__ int sIdx[TN];
    __shared__ float sM[TN];

    const int tid = threadIdx.x;
    const int tx = tid % NTX, ty = tid / NTX;
    const int n0 = blockIdx.x * TN;
    const int nb = ty * RN, db = tx * RD;

    ull acc[RN][NP];
#pragma unroll
    for (int i = 0; i < RN; ++i)
#pragma unroll
        for (int p = 0; p < NP; ++p) acc[i][p] = 0ULL;

    int rowAct[RPT];
#pragma unroll
    for (int j = 0; j < RPT; ++j) rowAct[j] = 0;

    for (int k = 0; k < 27; ++k) {
        int myAny = 0;
#pragma unroll
        for (int j = 0; j < RPT; ++j) {
            int i = tid + j * NTH;
            int n = n0 + i;
            int idx = (n < N) ? nbr[n * 27 + k] : N;
            float m = ((unsigned)idx < (unsigned)N) ? pm[idx] : 0.f;
            sIdx[i] = idx;
            sM[i] = m;
            int nz = (m != 0.f);
            myAny |= nz;
            rowAct[j] |= nz;
        }
        if (!__syncthreads_or(myAny)) continue;   // exact: zero contribution

        const float* Wk = W + (size_t)k * CIN * COUT;
        for (int i = tid; i < CIN * COUT; i += NTH) sW[i] = Wk[i];
        for (int i = tid; i < TN * VEC; i += NTH) {
            int n = i / VEC, c4 = (i - n * VEC) * 4;
            int idx = sIdx[n];
            float4 v = make_float4(0.f, 0.f, 0.f, 0.f);
            if ((unsigned)idx < (unsigned)N) {
                float m = sM[n];
                if (m != 0.f) {
                    v = *reinterpret_cast<const float4*>(
                        feat + (size_t)idx * CIN + c4);
                    v.x *= m; v.y *= m; v.z *= m; v.w *= m;
                }
            }
            *reinterpret_cast<float4*>(sF + n * CP + c4) = v;
        }
        __syncthreads();

#pragma unroll
        for (int c4 = 0; c4 < CIN; c4 += 4) {
            float4 A[RN];
#pragma unroll
            for (int i = 0; i < RN; ++i)
                A[i] = *reinterpret_cast<const float4*>(sF + (nb + i) * CP + c4);
#pragma unroll
            for (int cc = 0; cc < 4; ++cc) {
                ull as[RN];
#pragma unroll
                for (int i = 0; i < RN; ++i) {
                    float v = (cc == 0) ? A[i].x : (cc == 1) ? A[i].y
                             : (cc == 2) ? A[i].z : A[i].w;
                    as[i] = pk2(v, v);
                }
                const float* wrow = sW + (c4 + cc) * COUT + db;
#pragma unroll
                for (int u = 0; u < NU; ++u) {
                    float4 B = *reinterpret_cast<const float4*>(wrow + 4 * u);
                    ull b0 = pk2(B.x, B.y), b1 = pk2(B.z, B.w);
#pragma unroll
                    for (int i = 0; i < RN; ++i) {
                        fma2(acc[i][2 * u], as[i], b0);
                        fma2(acc[i][2 * u + 1], as[i], b1);
                    }
                }
            }
        }
    }

#pragma unroll
    for (int j = 0; j < RPT; ++j) {
        int n = n0 + tid + j * NTH;
        if (n < N) act[n] = (unsigned char)rowAct[j];
    }

#pragma unroll
    for (int i = 0; i < RN; ++i) {
        int n = n0 + nb + i;
        if (n < N) {
#pragma unroll
            for (int u = 0; u < NU; ++u) {
                float2 p0 = up2(acc[i][2 * u]), p1 = up2(acc[i][2 * u + 1]);
                float4 o = make_float4(p0.x, p0.y, p1.x, p1.y);
                *reinterpret_cast<float4*>(out + (size_t)n * COUT + db + 4 * u) = o;
            }
        }
    }
}

// ---------------------------------------------------------------------------
// Score head (Cout=2) + ppn concat + threshold mask — BATCHED pointer-chase:
// all 27 neighbor indices then act flags preloaded into regs (MLP), gather
// only provably-nonzero rows. Math order identical to proven form.
// softmax([s0,s1])[1] > 0.8  <=>  1/(1+exp(s0-s1)) > 0.8
// ---------------------------------------------------------------------------
template <int CIN, bool ACT>
__global__ void score_ppn_mask(const float* __restrict__ feat,
                               const int* __restrict__ nbr,
                               const float* __restrict__ Ws,
                               const int* __restrict__ coords,
                               const unsigned char* __restrict__ act,
                               float* __restrict__ ppn,
                               float* __restrict__ mask, int N) {
    __shared__ float sW[27 * 2 * CIN];  // [k][d][c]
    for (int i = threadIdx.x; i < 27 * CIN * 2; i += blockDim.x) {
        int k = i / (CIN * 2);
        int r = i - k * (CIN * 2);
        int c = r >> 1, d = r & 1;
        sW[(k * 2 + d) * CIN + c] = Ws[i];
    }
    __syncthreads();
    int n = blockIdx.x * blockDim.x + threadIdx.x;
    if (n >= N) return;

    int idxs[27];
#pragma unroll
    for (int k = 0; k < 27; ++k) idxs[k] = nbr[n * 27 + k];
    bool live[27];
#pragma unroll
    for (int k = 0; k < 27; ++k) {
        bool v = (unsigned)idxs[k] < (unsigned)N;
        if (ACT) v = v && (act[idxs[k]] != 0);
        live[k] = v;
    }

    float a0 = 0.f, a1 = 0.f;
#pragma unroll
    for (int k = 0; k < 27; ++k) {
        if (live[k]) {
            const float4* fr = reinterpret_cast<const float4*>(feat + (size_t)idxs[k] * CIN);
            const float4* w0 = reinterpret_cast<const float4*>(sW + (k * 2 + 0) * CIN);
            const float4* w1 = reinterpret_cast<const float4*>(sW + (k * 2 + 1) * CIN);
#pragma unroll
            for (int j = 0; j < CIN / 4; ++j) {
                float4 v = fr[j], x = w0[j], y = w1[j];
                a0 += v.x * x.x + v.y * x.y + v.z * x.z + v.w * x.w;
                a1 += v.x * y.x + v.y * y.y + v.z * y.z + v.w * y.w;
            }
        }
    }
    ppn[(size_t)n * 6 + 0] = (float)coords[n * 4 + 0];
    ppn[(size_t)n * 6 + 1] = (float)coords[n * 4 + 1];
    ppn[(size_t)n * 6 + 2] = (float)coords[n * 4 + 2];
    ppn[(size_t)n * 6 + 3] = (float)coords[n * 4 + 3];
    ppn[(size_t)n * 6 + 4] = a0;
    ppn[(size_t)n * 6 + 5] = a1;
    float p = 1.f / (1.f + expf(a0 - a1));
    mask[n] = (p > 0.8f) ? 1.f : 0.f;
}

// Fine heads fused, batched pointer-chase: points[n, 0:3|3:5|5:10].
__global__ void heads_kernel(const float* __restrict__ z,
                             const int* __restrict__ nbr,
                             const float* __restrict__ Wp,
                             const float* __restrict__ Wsc,
                             const float* __restrict__ Wt,
                             const unsigned char* __restrict__ act,
                             float* __restrict__ points, int N) {
    __shared__ float sW[27 * 10 * 16];  // [k][d][c]
    for (int i = threadIdx.x; i < 27 * 16 * 3; i += blockDim.x) {
        int k = i / 48; int r = i - k * 48; int c = r / 3; int d = r - c * 3;
        sW[(k * 10 + d) * 16 + c] = Wp[i];
    }
    for (int i = threadIdx.x; i < 27 * 16 * 2; i += blockDim.x) {
        int k = i / 32; int r = i - k * 32; int c = r >> 1; int d = r & 1;
        sW[(k * 10 + 3 + d) * 16 + c] = Wsc[i];
    }
    for (int i = threadIdx.x; i < 27 * 16 * 5; i += blockDim.x) {
        int k = i / 80; int r = i - k * 80; int c = r / 5; int d = r - c * 5;
        sW[(k * 10 + 5 + d) * 16 + c] = Wt[i];
    }
    __syncthreads();
    int n = blockIdx.x * blockDim.x + threadIdx.x;
    if (n >= N) return;

    int idxs[27];
#pragma unroll
    for (int k = 0; k < 27; ++k) idxs[k] = nbr[n * 27 + k];
    bool live[27];
#pragma unroll
    for (int k = 0; k < 27; ++k)
        live[k] = ((unsigned)idxs[k] < (unsigned)N) && (act[idxs[k]] != 0);

    float acc[10];
#pragma unroll
    for (int d = 0; d < 10; ++d) acc[d] = 0.f;

#pragma unroll
    for (int k = 0; k < 27; ++k) {
        if (live[k]) {
            const float4* zr = reinterpret_cast<const float4*>(z + (size_t)idxs[k] * 16);
            float4 v0 = zr[0], v1 = zr[1], v2 = zr[2], v3 = zr[3];
#pragma unroll
            for (int d = 0; d < 10; ++d) {
                const float4* wr = reinterpret_cast<const float4*>(sW + (k * 10 + d) * 16);
                float4 w0 = wr[0], w1 = wr[1], w2 = wr[2], w3 = wr[3];
                acc[d] += v0.x * w0.x + v0.y * w0.y + v0.z * w0.z + v0.w * w0.w
                        + v1.x * w1.x + v1.y * w1.y + v1.z * w1.z + v1.w * w1.w
                        + v2.x * w2.x + v2.y * w2.y + v2.z * w2.z + v2.w * w2.w
                        + v3.x * w3.x + v3.y * w3.y + v3.z * w3.z + v3.w * w3.w;
            }
        }
    }
#pragma unroll
    for (int d = 0; d < 10; ++d) points[(size_t)n * 10 + d] = acc[d];
}

// ---------------------------------------------------------------------------
static constexpr int smem_sub(int CCH, int COUT, int TN) {
    return (CCH * COUT + TN * (CCH + 4) + 32) * (int)sizeof(float);
}

extern "C" void kernel_launch(void* const* d_in, const int* in_sizes, int n_in,
                              void* d_out, int out_size) {
    const float* feat1 = (const float*)d_in[0];
    const float* feat2 = (const float*)d_in[1];
    const float* feat3 = (const float*)d_in[2];
    const float* W1  = (const float*)d_in[3];
    const float* W1s = (const float*)d_in[4];
    const float* W2  = (const float*)d_in[5];
    const float* W2s = (const float*)d_in[6];
    const float* W3  = (const float*)d_in[7];
    const float* W3p = (const float*)d_in[8];
    const float* W3s = (const float*)d_in[9];
    const float* W3t = (const float*)d_in[10];
    const int* nbr1 = (const int*)d_in[11];
    const int* nbr2 = (const int*)d_in[12];
    const int* nbr3 = (const int*)d_in[13];
    const int* parent2 = (const int*)d_in[14];
    const int* parent3 = (const int*)d_in[15];
    const int* coords1 = (const int*)d_in[16];
    const int* coords2 = (const int*)d_in[17];

    const int N1 = in_sizes[0] / 80;
    const int N2 = in_sizes[1] / 48;
    const int N3 = in_sizes[2] / 16;

    float* out = (float*)d_out;
    float* points = out;
    float* ppn1  = points + (size_t)N3 * 10;
    float* ppn2  = ppn1 + (size_t)N1 * 6;
    float* mask1 = ppn2 + (size_t)N2 * 6;
    float* mask2 = mask1 + N1;

    float *y1, *y2, *z, *pm2, *pm3;
    unsigned char *act2, *act3;
    cudaGetSymbolAddress((void**)&y1, g_y1);
    cudaGetSymbolAddress((void**)&y2, g_y2);
    cudaGetSymbolAddress((void**)&z, g_z);
    cudaGetSymbolAddress((void**)&pm2, g_pm2);
    cudaGetSymbolAddress((void**)&pm3, g_pm3);
    cudaGetSymbolAddress((void**)&act2, g_act2);
    cudaGetSymbolAddress((void**)&act3, g_act3);

    // --- Level 1 (coarse, 80ch): chunked CCH=40, 35.4KB smem, 4 blk/SM ---
    subconv2<80, 80, 128, 4, 20, 4, 40, 4>
        <<<(N1 + 127) / 128, 128, smem_sub(40, 80, 128)>>>(feat1, nbr1, W1, y1, N1);
    score_ppn_mask<80, false><<<(N1 + 255) / 256, 256>>>(
        y1, nbr1, W1s, coords1, nullptr, ppn1, mask1, N1);

    // --- Level 2 (mid, 48ch): pm2 precompute + proven conv (minBlocks=5) ---
    premask<<<(N2 + 255) / 256, 256>>>(parent2, mask1, pm2, N2);
    subconv2m<48, 48, 128, 4, 12, 4, 5>
        <<<(N2 + 127) / 128, 128, smem_sub(48, 48, 128)>>>(
            feat2, nbr2, W2, pm2, y2, act2, N2);
    score_ppn_mask<48, true><<<(N2 + 255) / 256, 256>>>(
        y2, nbr2, W2s, coords2, act2, ppn2, mask2, N2);

    // --- Level 3 (fine, 16ch): pm3 precompute + masked conv + act flags ---
    premask<<<(N3 + 255) / 256, 256>>>(parent3, mask2, pm3, N3);
    subconv2m<16, 16, 256, 8, 4, 4, 1>
        <<<(N3 + 255) / 256, 128, smem_sub(16, 16, 256)>>>(
            feat3, nbr3, W3, pm3, z, act3, N3);
    heads_kernel<<<(N3 + 255) / 256, 256>>>(
        z, nbr3, W3p, W3s, W3t, act3, points, N3);
}